// round 1
// baseline (speedup 1.0000x reference)
#include <cuda_runtime.h>

// chamfer_3DDist: B=16, N=M=4096, 3D points.
// Output layout (float32): [dist1 (B*N) | dist2 (B*M) | idx1 (B*N) | idx2 (B*M)]
//
// One launch, blockIdx.z selects direction (0: queries=xyz1/cands=xyz2, 1: swapped).
// Each thread owns U=2 query points; candidate chunk of 1024 points staged in
// shared memory as float4 (x,y,z, ||p||^2). Distance uses the reference's exact
// fp32 rounding sequence: d = (x2 + y2) - 2*dot  with dot as an FMA chain,
// squared norms as mul+add (no contraction). Strict '<' keeps first argmin.

#define BT    256   // threads per block
#define UQ    2     // queries per thread
#define CHUNK 1024  // candidates staged per smem tile
#define NPTS  4096
#define BATCH 16

__global__ __launch_bounds__(BT) void chamfer_nn_kernel(
    const float* __restrict__ xyz1,
    const float* __restrict__ xyz2,
    float* __restrict__ out)
{
    const int dir = blockIdx.z;              // 0 or 1
    const int b   = blockIdx.y;              // batch
    const float* __restrict__ q = (dir == 0) ? xyz1 : xyz2;
    const float* __restrict__ c = (dir == 0) ? xyz2 : xyz1;

    const int BN = BATCH * NPTS;             // 65536 per section
    float* __restrict__ dist_out = out + dir * BN;            // dist1 @0, dist2 @BN
    float* __restrict__ idx_out  = out + 2 * BN + dir * BN;   // idx1 @2BN, idx2 @3BN

    const int tile_q0 = blockIdx.x * (BT * UQ);  // query offset within this batch

    // Load this thread's queries and precompute squared norms with the
    // reference's rounding: ((x0*x0 + x1*x1) + x2*x2), no FMA contraction.
    float qx[UQ], qy[UQ], qz[UQ], q2[UQ];
    float best[UQ];
    int   bidx[UQ];
#pragma unroll
    for (int u = 0; u < UQ; ++u) {
        const int qi = b * NPTS + tile_q0 + u * BT + threadIdx.x;
        const float* p = q + 3 * qi;
        const float x0 = p[0], x1 = p[1], x2v = p[2];
        qx[u] = x0; qy[u] = x1; qz[u] = x2v;
        q2[u] = __fadd_rn(__fadd_rn(__fmul_rn(x0, x0), __fmul_rn(x1, x1)),
                          __fmul_rn(x2v, x2v));
        best[u] = 3.402823466e38f;
        bidx[u] = 0;
    }

    __shared__ float4 sc[CHUNK];
    const int cbase3 = b * NPTS * 3;

    for (int c0 = 0; c0 < NPTS; c0 += CHUNK) {
        // Cooperative stage of candidate chunk: (y0,y1,y2, y2norm)
        for (int j = threadIdx.x; j < CHUNK; j += BT) {
            const float* p = c + cbase3 + 3 * (c0 + j);
            const float y0 = p[0], y1 = p[1], y2v = p[2];
            const float w = __fadd_rn(__fadd_rn(__fmul_rn(y0, y0), __fmul_rn(y1, y1)),
                                      __fmul_rn(y2v, y2v));
            sc[j] = make_float4(y0, y1, y2v, w);
        }
        __syncthreads();

#pragma unroll 8
        for (int j = 0; j < CHUNK; ++j) {
            const float4 y = sc[j];
#pragma unroll
            for (int u = 0; u < UQ; ++u) {
                // dot as FMA chain (matches XLA/Eigen K=3 contraction)
                float xy = __fmaf_rn(qz[u], y.z,
                            __fmaf_rn(qy[u], y.y,
                              __fmul_rn(qx[u], y.x)));
                // (x2 + y2) - 2*xy : 2*xy is exact, so single-rounded fma form
                float s = __fadd_rn(q2[u], y.w);
                float d = __fmaf_rn(-2.0f, xy, s);
                if (d < best[u]) { best[u] = d; bidx[u] = c0 + j; }
            }
        }
        __syncthreads();
    }

#pragma unroll
    for (int u = 0; u < UQ; ++u) {
        const int qlocal = tile_q0 + u * BT + threadIdx.x;   // [0, NPTS)
        dist_out[b * NPTS + qlocal] = best[u];
        idx_out [b * NPTS + qlocal] = (float)bidx[u];
    }
}

extern "C" void kernel_launch(void* const* d_in, const int* in_sizes, int n_in,
                              void* d_out, int out_size)
{
    (void)in_sizes; (void)n_in; (void)out_size;
    const float* xyz1 = (const float*)d_in[0];
    const float* xyz2 = (const float*)d_in[1];
    float* out = (float*)d_out;

    dim3 grid(NPTS / (BT * UQ), BATCH, 2);   // (8, 16, 2) = 256 blocks
    dim3 block(BT);
    chamfer_nn_kernel<<<grid, block>>>(xyz1, xyz2, out);
}

// round 2
// speedup vs baseline: 1.1907x; 1.1907x over previous
#include <cuda_runtime.h>

// chamfer_3DDist: B=16, N=M=4096, 3D points.
// Output (float32): [dist1 (B*N) | dist2 (B*M) | idx1 (B*N) | idx2 (B*M)]
//
// Round-2 kernel: packed f32x2 math (FFMA2) processes 2 candidates per
// instruction with bit-identical per-lane rounding to the scalar reference
// sequence:  xy = fma(z, fma(y, mul(x)));  d = fma(-2, xy, x2 + y2).
// 64-thread blocks x 128 queries -> 1024 blocks, fully resident in one wave.

#define BT    64     // threads per block
#define UQ    2      // queries per thread
#define CHUNK 1024   // candidates staged per smem tile
#define NPTS  4096
#define BATCH 16

typedef unsigned long long u64;

__device__ __forceinline__ u64 pack2(float lo, float hi) {
    u64 r; asm("mov.b64 %0, {%1, %2};" : "=l"(r) : "f"(lo), "f"(hi)); return r;
}
__device__ __forceinline__ void unpack2(u64 v, float& lo, float& hi) {
    asm("mov.b64 {%0, %1}, %2;" : "=f"(lo), "=f"(hi) : "l"(v));
}
__device__ __forceinline__ u64 fma2(u64 a, u64 b, u64 c) {
    u64 d; asm("fma.rn.f32x2 %0, %1, %2, %3;" : "=l"(d) : "l"(a), "l"(b), "l"(c)); return d;
}
__device__ __forceinline__ u64 mul2(u64 a, u64 b) {
    u64 d; asm("mul.rn.f32x2 %0, %1, %2;" : "=l"(d) : "l"(a), "l"(b)); return d;
}
__device__ __forceinline__ u64 add2(u64 a, u64 b) {
    u64 d; asm("add.rn.f32x2 %0, %1, %2;" : "=l"(d) : "l"(a), "l"(b)); return d;
}

__global__ __launch_bounds__(BT) void chamfer_nn_kernel(
    const float* __restrict__ xyz1,
    const float* __restrict__ xyz2,
    float* __restrict__ out)
{
    const int dir = blockIdx.z;
    const int b   = blockIdx.y;
    const float* __restrict__ q = (dir == 0) ? xyz1 : xyz2;
    const float* __restrict__ c = (dir == 0) ? xyz2 : xyz1;

    const int BN = BATCH * NPTS;
    float* __restrict__ dist_out = out + dir * BN;
    float* __restrict__ idx_out  = out + 2 * BN + dir * BN;

    const int tile_q0 = blockIdx.x * (BT * UQ);

    // Per-thread query registers: packed broadcast (q,q) for f32x2 lanes.
    u64 qx2[UQ], qy2[UQ], qz2[UQ], q22[UQ];
    float best[UQ];
    int   bidx[UQ];
#pragma unroll
    for (int u = 0; u < UQ; ++u) {
        const int qi = b * NPTS + tile_q0 + u * BT + threadIdx.x;
        const float* p = q + 3 * qi;
        const float x0 = p[0], x1 = p[1], x2v = p[2];
        // reference rounding: ((x0*x0 + x1*x1) + x2*x2), no contraction
        const float s = __fadd_rn(__fadd_rn(__fmul_rn(x0, x0), __fmul_rn(x1, x1)),
                                  __fmul_rn(x2v, x2v));
        qx2[u] = pack2(x0, x0);
        qy2[u] = pack2(x1, x1);
        qz2[u] = pack2(x2v, x2v);
        q22[u] = pack2(s, s);
        best[u] = 3.402823466e38f;
        bidx[u] = 0;
    }
    const u64 m2two = pack2(-2.0f, -2.0f);

    // smem: per candidate-pair p (cands 2p, 2p+1):
    //   sc[p][0] = (x_2p, x_2p1, y_2p, y_2p1)
    //   sc[p][1] = (z_2p, z_2p1, w_2p, w_2p1)   w = ||y||^2 (reference rounding)
    __shared__ float4 sc[CHUNK / 2][2];
    const int cbase3 = b * NPTS * 3;

    for (int c0 = 0; c0 < NPTS; c0 += CHUNK) {
        for (int pp = threadIdx.x; pp < CHUNK / 2; pp += BT) {
            const float* p0 = c + cbase3 + 3 * (c0 + 2 * pp);
            const float a0 = p0[0], a1 = p0[1], a2 = p0[2];
            const float b0 = p0[3], b1 = p0[4], b2 = p0[5];
            const float w0 = __fadd_rn(__fadd_rn(__fmul_rn(a0, a0), __fmul_rn(a1, a1)),
                                       __fmul_rn(a2, a2));
            const float w1 = __fadd_rn(__fadd_rn(__fmul_rn(b0, b0), __fmul_rn(b1, b1)),
                                       __fmul_rn(b2, b2));
            sc[pp][0] = make_float4(a0, b0, a1, b1);
            sc[pp][1] = make_float4(a2, b2, w0, w1);
        }
        __syncthreads();

        const ulonglong2* __restrict__ sp = (const ulonglong2*)sc;

#pragma unroll 8
        for (int p = 0; p < CHUNK / 2; ++p) {
            const ulonglong2 A = sp[2 * p];      // (X2, Y2)
            const ulonglong2 Bv = sp[2 * p + 1]; // (Z2, W2)
            const int jbase = c0 + 2 * p;
#pragma unroll
            for (int u = 0; u < UQ; ++u) {
                // packed dot, per-lane bit-identical to scalar reference chain
                u64 xy2 = fma2(qz2[u], Bv.x, fma2(qy2[u], A.y, mul2(qx2[u], A.x)));
                u64 d2  = fma2(m2two, xy2, add2(q22[u], Bv.y));
                float d0, d1; unpack2(d2, d0, d1);
                // first-occurrence argmin: take d1 only if strictly smaller
                const bool p1 = d1 < d0;
                const float m = fminf(d0, d1);
                const int  mi = p1 ? (jbase + 1) : jbase;
                if (m < best[u]) { best[u] = m; bidx[u] = mi; }
            }
        }
        __syncthreads();
    }

#pragma unroll
    for (int u = 0; u < UQ; ++u) {
        const int qlocal = tile_q0 + u * BT + threadIdx.x;
        dist_out[b * NPTS + qlocal] = best[u];
        idx_out [b * NPTS + qlocal] = (float)bidx[u];
    }
}

extern "C" void kernel_launch(void* const* d_in, const int* in_sizes, int n_in,
                              void* d_out, int out_size)
{
    (void)in_sizes; (void)n_in; (void)out_size;
    const float* xyz1 = (const float*)d_in[0];
    const float* xyz2 = (const float*)d_in[1];
    float* out = (float*)d_out;

    dim3 grid(NPTS / (BT * UQ), BATCH, 2);   // (32, 16, 2) = 1024 blocks
    dim3 block(BT);
    chamfer_nn_kernel<<<grid, block>>>(xyz1, xyz2, out);
}

// round 3
// speedup vs baseline: 1.2083x; 1.0148x over previous
#include <cuda_runtime.h>

// chamfer_3DDist: B=16, N=M=4096, 3D points.
// Output (float32): [dist1 (B*N) | dist2 (B*M) | idx1 (B*N) | idx2 (B*M)]
//
// Round-3: candidate-split x2 to double resident warps (occupancy was
// grid-limited at 13.8 warps/SM, issue=68.7%). Each main block scans half the
// candidates and writes partial (best, idx) to device scratch; a merge kernel
// combines splits with split-0-wins tie-breaking (preserves first-occurrence
// argmin and bit-identical distances). Packed f32x2 math unchanged.

#define BT    64     // threads per block
#define UQ    2      // queries per thread
#define CHUNK 1024   // candidates staged per smem tile
#define NPTS  4096
#define BATCH 16
#define NSPLIT 2
#define CPS   (NPTS / NSPLIT)   // candidates per split

typedef unsigned long long u64;

// scratch: [split][dir][b*NPTS + q]
__device__ float g_best[NSPLIT][2][BATCH * NPTS];
__device__ int   g_bidx[NSPLIT][2][BATCH * NPTS];

__device__ __forceinline__ u64 pack2(float lo, float hi) {
    u64 r; asm("mov.b64 %0, {%1, %2};" : "=l"(r) : "f"(lo), "f"(hi)); return r;
}
__device__ __forceinline__ void unpack2(u64 v, float& lo, float& hi) {
    asm("mov.b64 {%0, %1}, %2;" : "=f"(lo), "=f"(hi) : "l"(v));
}
__device__ __forceinline__ u64 fma2(u64 a, u64 b, u64 c) {
    u64 d; asm("fma.rn.f32x2 %0, %1, %2, %3;" : "=l"(d) : "l"(a), "l"(b), "l"(c)); return d;
}
__device__ __forceinline__ u64 mul2(u64 a, u64 b) {
    u64 d; asm("mul.rn.f32x2 %0, %1, %2;" : "=l"(d) : "l"(a), "l"(b)); return d;
}
__device__ __forceinline__ u64 add2(u64 a, u64 b) {
    u64 d; asm("add.rn.f32x2 %0, %1, %2;" : "=l"(d) : "l"(a), "l"(b)); return d;
}

__global__ __launch_bounds__(BT) void chamfer_nn_main(
    const float* __restrict__ xyz1,
    const float* __restrict__ xyz2)
{
    const int dir   = blockIdx.z & 1;
    const int split = blockIdx.z >> 1;
    const int b     = blockIdx.y;
    const float* __restrict__ q = (dir == 0) ? xyz1 : xyz2;
    const float* __restrict__ c = (dir == 0) ? xyz2 : xyz1;

    const int tile_q0 = blockIdx.x * (BT * UQ);

    u64 qx2[UQ], qy2[UQ], qz2[UQ], q22[UQ];
    float best[UQ];
    int   bidx[UQ];
#pragma unroll
    for (int u = 0; u < UQ; ++u) {
        const int qi = b * NPTS + tile_q0 + u * BT + threadIdx.x;
        const float* p = q + 3 * qi;
        const float x0 = p[0], x1 = p[1], x2v = p[2];
        // reference rounding: ((x0*x0 + x1*x1) + x2*x2), no contraction
        const float s = __fadd_rn(__fadd_rn(__fmul_rn(x0, x0), __fmul_rn(x1, x1)),
                                  __fmul_rn(x2v, x2v));
        qx2[u] = pack2(x0, x0);
        qy2[u] = pack2(x1, x1);
        qz2[u] = pack2(x2v, x2v);
        q22[u] = pack2(s, s);
        best[u] = 3.402823466e38f;
        bidx[u] = 0;
    }
    const u64 m2two = pack2(-2.0f, -2.0f);

    // smem per candidate pair p (cands 2p, 2p+1):
    //   sc[p][0] = (x_2p, x_2p1, y_2p, y_2p1)
    //   sc[p][1] = (z_2p, z_2p1, w_2p, w_2p1)   w = ||y||^2 (reference rounding)
    __shared__ float4 sc[CHUNK / 2][2];
    const int cbase3 = b * NPTS * 3;
    const int cstart = split * CPS;

    for (int c0 = cstart; c0 < cstart + CPS; c0 += CHUNK) {
        for (int pp = threadIdx.x; pp < CHUNK / 2; pp += BT) {
            const float* p0 = c + cbase3 + 3 * (c0 + 2 * pp);
            const float a0 = p0[0], a1 = p0[1], a2 = p0[2];
            const float b0 = p0[3], b1 = p0[4], b2 = p0[5];
            const float w0 = __fadd_rn(__fadd_rn(__fmul_rn(a0, a0), __fmul_rn(a1, a1)),
                                       __fmul_rn(a2, a2));
            const float w1 = __fadd_rn(__fadd_rn(__fmul_rn(b0, b0), __fmul_rn(b1, b1)),
                                       __fmul_rn(b2, b2));
            sc[pp][0] = make_float4(a0, b0, a1, b1);
            sc[pp][1] = make_float4(a2, b2, w0, w1);
        }
        __syncthreads();

        const ulonglong2* __restrict__ sp = (const ulonglong2*)sc;

#pragma unroll 16
        for (int p = 0; p < CHUNK / 2; ++p) {
            const ulonglong2 A  = sp[2 * p];      // (X2, Y2)
            const ulonglong2 Bv = sp[2 * p + 1];  // (Z2, W2)
            const int jbase = c0 + 2 * p;
#pragma unroll
            for (int u = 0; u < UQ; ++u) {
                // packed dot, per-lane bit-identical to scalar reference chain
                u64 xy2 = fma2(qz2[u], Bv.x, fma2(qy2[u], A.y, mul2(qx2[u], A.x)));
                u64 d2  = fma2(m2two, xy2, add2(q22[u], Bv.y));
                float d0, d1; unpack2(d2, d0, d1);
                // first-occurrence argmin: take d1 only if strictly smaller
                const bool p1 = d1 < d0;
                const float m = fminf(d0, d1);
                const int  mi = p1 ? (jbase + 1) : jbase;
                if (m < best[u]) { best[u] = m; bidx[u] = mi; }
            }
        }
        __syncthreads();
    }

#pragma unroll
    for (int u = 0; u < UQ; ++u) {
        const int qg = b * NPTS + tile_q0 + u * BT + threadIdx.x;
        g_best[split][dir][qg] = best[u];
        g_bidx[split][dir][qg] = bidx[u];
    }
}

// Merge splits: split 0 wins ties (lower candidate indices) -> exact
// first-occurrence argmin semantics.
__global__ __launch_bounds__(256) void chamfer_nn_merge(float* __restrict__ out)
{
    const int t = blockIdx.x * blockDim.x + threadIdx.x;   // [0, 2*BATCH*NPTS)
    const int BN  = BATCH * NPTS;
    const int dir = t / BN;
    const int qg  = t - dir * BN;

    const float b0 = g_best[0][dir][qg];
    const float b1 = g_best[1][dir][qg];
    const int   i0 = g_bidx[0][dir][qg];
    const int   i1 = g_bidx[1][dir][qg];

    const bool take1 = b1 < b0;
    out[dir * BN + qg]          = take1 ? b1 : b0;
    out[2 * BN + dir * BN + qg] = (float)(take1 ? i1 : i0);
}

extern "C" void kernel_launch(void* const* d_in, const int* in_sizes, int n_in,
                              void* d_out, int out_size)
{
    (void)in_sizes; (void)n_in; (void)out_size;
    const float* xyz1 = (const float*)d_in[0];
    const float* xyz2 = (const float*)d_in[1];
    float* out = (float*)d_out;

    dim3 grid(NPTS / (BT * UQ), BATCH, 2 * NSPLIT);   // (32, 16, 4) = 2048 blocks
    chamfer_nn_main<<<grid, BT>>>(xyz1, xyz2);

    chamfer_nn_merge<<<(2 * BATCH * NPTS) / 256, 256>>>(out);
}

// round 4
// speedup vs baseline: 1.4642x; 1.2117x over previous
#include <cuda_runtime.h>

// chamfer_3DDist: B=16, N=M=4096, 3D points.
// Output (float32): [dist1 (B*N) | dist2 (B*M) | idx1 (B*N) | idx2 (B*M)]
//
// Round-4: quad-deferred argmin. Inner loop tracks only (best distance,
// winning quad-of-4 index) -> bookkeeping drops from ~6.4 to ~1.5 alu ops per
// 2-candidate unit. The finalize kernel recomputes the 4 distances of the
// winning quad bit-identically and resolves the exact first-occurrence index
// via equality scan. Packed f32x2 math (full-rate FFMA2) unchanged.

#define BT    64     // threads per block
#define UQ    4      // queries per thread
#define CHUNK 1024   // candidates staged per smem tile
#define NPTS  4096
#define BATCH 16
#define NSPLIT 2
#define CPS   (NPTS / NSPLIT)

typedef unsigned long long u64;

// scratch: [split][dir][b*NPTS + q]
__device__ float g_best [NSPLIT][2][BATCH * NPTS];
__device__ int   g_jquad[NSPLIT][2][BATCH * NPTS];

__device__ __forceinline__ u64 pack2(float lo, float hi) {
    u64 r; asm("mov.b64 %0, {%1, %2};" : "=l"(r) : "f"(lo), "f"(hi)); return r;
}
__device__ __forceinline__ void unpack2(u64 v, float& lo, float& hi) {
    asm("mov.b64 {%0, %1}, %2;" : "=f"(lo), "=f"(hi) : "l"(v));
}
__device__ __forceinline__ u64 fma2(u64 a, u64 b, u64 c) {
    u64 d; asm("fma.rn.f32x2 %0, %1, %2, %3;" : "=l"(d) : "l"(a), "l"(b), "l"(c)); return d;
}
__device__ __forceinline__ u64 mul2(u64 a, u64 b) {
    u64 d; asm("mul.rn.f32x2 %0, %1, %2;" : "=l"(d) : "l"(a), "l"(b)); return d;
}
__device__ __forceinline__ u64 add2(u64 a, u64 b) {
    u64 d; asm("add.rn.f32x2 %0, %1, %2;" : "=l"(d) : "l"(a), "l"(b)); return d;
}

// Reference-rounded squared norm: ((x*x + y*y) + z*z), no contraction.
__device__ __forceinline__ float sqnorm_ref(float x, float y, float z) {
    return __fadd_rn(__fadd_rn(__fmul_rn(x, x), __fmul_rn(y, y)), __fmul_rn(z, z));
}
// Reference-rounded distance: fma(-2, dot, x2+y2) with dot = fma chain.
__device__ __forceinline__ float dist_ref(float qx, float qy, float qz, float q2,
                                          float cx, float cy, float cz, float c2) {
    float xy = __fmaf_rn(qz, cz, __fmaf_rn(qy, cy, __fmul_rn(qx, cx)));
    return __fmaf_rn(-2.0f, xy, __fadd_rn(q2, c2));
}

__global__ __launch_bounds__(BT) void chamfer_nn_main(
    const float* __restrict__ xyz1,
    const float* __restrict__ xyz2)
{
    const int dir   = blockIdx.z & 1;
    const int split = blockIdx.z >> 1;
    const int b     = blockIdx.y;
    const float* __restrict__ q = (dir == 0) ? xyz1 : xyz2;
    const float* __restrict__ c = (dir == 0) ? xyz2 : xyz1;

    const int tile_q0 = blockIdx.x * (BT * UQ);

    u64 qx2[UQ], qy2[UQ], qz2[UQ], q22[UQ];
    float best[UQ];
    int   jqd[UQ];
#pragma unroll
    for (int u = 0; u < UQ; ++u) {
        const int qi = b * NPTS + tile_q0 + u * BT + threadIdx.x;
        const float* p = q + 3 * qi;
        const float x0 = p[0], x1 = p[1], x2v = p[2];
        const float s = sqnorm_ref(x0, x1, x2v);
        qx2[u] = pack2(x0, x0);
        qy2[u] = pack2(x1, x1);
        qz2[u] = pack2(x2v, x2v);
        q22[u] = pack2(s, s);
        best[u] = 3.402823466e38f;
        jqd[u]  = 0;
    }
    const u64 m2two = pack2(-2.0f, -2.0f);

    // smem per candidate pair p (cands 2p, 2p+1):
    //   sc[p][0] = (x_2p, x_2p1, y_2p, y_2p1)
    //   sc[p][1] = (z_2p, z_2p1, w_2p, w_2p1)   w = ||y||^2
    __shared__ float4 sc[CHUNK / 2][2];
    const int cbase3 = b * NPTS * 3;
    const int cstart = split * CPS;

    for (int c0 = cstart; c0 < cstart + CPS; c0 += CHUNK) {
        for (int pp = threadIdx.x; pp < CHUNK / 2; pp += BT) {
            const float* p0 = c + cbase3 + 3 * (c0 + 2 * pp);
            const float a0 = p0[0], a1 = p0[1], a2 = p0[2];
            const float b0 = p0[3], b1 = p0[4], b2 = p0[5];
            sc[pp][0] = make_float4(a0, b0, a1, b1);
            sc[pp][1] = make_float4(a2, b2, sqnorm_ref(a0, a1, a2),
                                            sqnorm_ref(b0, b1, b2));
        }
        __syncthreads();

        const ulonglong2* __restrict__ sp = (const ulonglong2*)sc;
        const int qbase = c0 >> 2;   // global quad index of first quad in chunk

#pragma unroll 8
        for (int k = 0; k < CHUNK / 4; ++k) {
            const ulonglong2 A0 = sp[4 * k + 0];  // (X2, Y2) cands 4k,4k+1
            const ulonglong2 B0 = sp[4 * k + 1];  // (Z2, W2)
            const ulonglong2 A1 = sp[4 * k + 2];  // cands 4k+2,4k+3
            const ulonglong2 B1 = sp[4 * k + 3];
#pragma unroll
            for (int u = 0; u < UQ; ++u) {
                u64 xya = fma2(qz2[u], B0.x, fma2(qy2[u], A0.y, mul2(qx2[u], A0.x)));
                u64 da  = fma2(m2two, xya, add2(q22[u], B0.y));
                u64 xyb = fma2(qz2[u], B1.x, fma2(qy2[u], A1.y, mul2(qx2[u], A1.x)));
                u64 db  = fma2(m2two, xyb, add2(q22[u], B1.y));
                float d0, d1, d2, d3;
                unpack2(da, d0, d1);
                unpack2(db, d2, d3);
                const float m = fminf(fminf(d0, d1), fminf(d2, d3));
                if (m < best[u]) jqd[u] = qbase + k;   // strict < keeps earliest quad
                best[u] = fminf(best[u], m);
            }
        }
        __syncthreads();
    }

#pragma unroll
    for (int u = 0; u < UQ; ++u) {
        const int qg = b * NPTS + tile_q0 + u * BT + threadIdx.x;
        g_best [split][dir][qg] = best[u];
        g_jquad[split][dir][qg] = jqd[u];
    }
}

// Finalize: resolve exact index inside the winning quad (bit-identical
// distance recompute, first equality wins) and merge splits (split 0 wins
// ties -> first-occurrence argmin).
__global__ __launch_bounds__(256) void chamfer_nn_finalize(
    const float* __restrict__ xyz1,
    const float* __restrict__ xyz2,
    float* __restrict__ out)
{
    const int t = blockIdx.x * blockDim.x + threadIdx.x;   // [0, 2*BATCH*NPTS)
    const int BN  = BATCH * NPTS;
    const int dir = t / BN;
    const int qg  = t - dir * BN;
    const int b   = qg / NPTS;

    const float* __restrict__ q = (dir == 0) ? xyz1 : xyz2;
    const float* __restrict__ c = (dir == 0) ? xyz2 : xyz1;

    const float* qp = q + 3 * qg;   // qg = b*NPTS + qlocal, q array is [B*NPTS,3]
    const float qx = qp[0], qy = qp[1], qz = qp[2];
    const float q2 = sqnorm_ref(qx, qy, qz);
    const int cbase3 = b * NPTS * 3;

    float bs[NSPLIT];
    int   ix[NSPLIT];
#pragma unroll
    for (int s = 0; s < NSPLIT; ++s) {
        bs[s] = g_best[s][dir][qg];
        const int base = g_jquad[s][dir][qg] * 4;
        int found = base;
        // scan descending so the FIRST (lowest k) match wins
#pragma unroll
        for (int k = 3; k >= 0; --k) {
            const float* cp = c + cbase3 + 3 * (base + k);
            const float d = dist_ref(qx, qy, qz, q2, cp[0], cp[1], cp[2],
                                     sqnorm_ref(cp[0], cp[1], cp[2]));
            if (d == bs[s]) found = base + k;
        }
        ix[s] = found;
    }

    const bool take1 = bs[1] < bs[0];
    out[dir * BN + qg]          = take1 ? bs[1] : bs[0];
    out[2 * BN + dir * BN + qg] = (float)(take1 ? ix[1] : ix[0]);
}

extern "C" void kernel_launch(void* const* d_in, const int* in_sizes, int n_in,
                              void* d_out, int out_size)
{
    (void)in_sizes; (void)n_in; (void)out_size;
    const float* xyz1 = (const float*)d_in[0];
    const float* xyz2 = (const float*)d_in[1];
    float* out = (float*)d_out;

    dim3 grid(NPTS / (BT * UQ), BATCH, 2 * NSPLIT);   // (16, 16, 4) = 1024 blocks
    chamfer_nn_main<<<grid, BT>>>(xyz1, xyz2);

    chamfer_nn_finalize<<<(2 * BATCH * NPTS) / 256, 256>>>(xyz1, xyz2, out);
}

// round 5
// speedup vs baseline: 1.5449x; 1.0551x over previous
#include <cuda_runtime.h>

// chamfer_3DDist: B=16, N=M=4096, 3D points.
// Output (float32): [dist1 (B*N) | dist2 (B*M) | idx1 (B*N) | idx2 (B*M)]
//
// Round-5: (a) SEL-form index update (pred-as-data, 4cyc) instead of
// predicated mov (pred-as-guard, 13cyc); (b) NSPLIT=4 restores 6.9 warps/SMSP;
// (c) oct-deferred argmin (group-of-8) cuts bookkeeping slots further.
// Finalize recomputes the winning oct bit-identically and resolves the exact
// first-occurrence index, then merges splits ascending (earliest split wins
// ties). Packed f32x2 math (full-rate FFMA2) carries the distance formula
// bit-identical to the reference.

#define BT    64     // threads per block
#define UQ    4      // queries per thread
#define CHUNK 1024   // candidates staged per smem tile
#define NPTS  4096
#define BATCH 16
#define NSPLIT 4
#define CPS   (NPTS / NSPLIT)   // 1024 candidates per split
#define GRP   8                 // deferral group size

typedef unsigned long long u64;

// scratch: [split][dir][b*NPTS + q]
__device__ float g_best[NSPLIT][2][BATCH * NPTS];
__device__ int   g_jgrp[NSPLIT][2][BATCH * NPTS];

__device__ __forceinline__ u64 pack2(float lo, float hi) {
    u64 r; asm("mov.b64 %0, {%1, %2};" : "=l"(r) : "f"(lo), "f"(hi)); return r;
}
__device__ __forceinline__ void unpack2(u64 v, float& lo, float& hi) {
    asm("mov.b64 {%0, %1}, %2;" : "=f"(lo), "=f"(hi) : "l"(v));
}
__device__ __forceinline__ u64 fma2(u64 a, u64 b, u64 c) {
    u64 d; asm("fma.rn.f32x2 %0, %1, %2, %3;" : "=l"(d) : "l"(a), "l"(b), "l"(c)); return d;
}
__device__ __forceinline__ u64 mul2(u64 a, u64 b) {
    u64 d; asm("mul.rn.f32x2 %0, %1, %2;" : "=l"(d) : "l"(a), "l"(b)); return d;
}
__device__ __forceinline__ u64 add2(u64 a, u64 b) {
    u64 d; asm("add.rn.f32x2 %0, %1, %2;" : "=l"(d) : "l"(a), "l"(b)); return d;
}

// Reference-rounded squared norm: ((x*x + y*y) + z*z), no contraction.
__device__ __forceinline__ float sqnorm_ref(float x, float y, float z) {
    return __fadd_rn(__fadd_rn(__fmul_rn(x, x), __fmul_rn(y, y)), __fmul_rn(z, z));
}
// Reference-rounded distance: fma(-2, dot, x2+y2) with dot = fma chain.
__device__ __forceinline__ float dist_ref(float qx, float qy, float qz, float q2,
                                          float cx, float cy, float cz) {
    float c2 = sqnorm_ref(cx, cy, cz);
    float xy = __fmaf_rn(qz, cz, __fmaf_rn(qy, cy, __fmul_rn(qx, cx)));
    return __fmaf_rn(-2.0f, xy, __fadd_rn(q2, c2));
}

__global__ __launch_bounds__(BT) void chamfer_nn_main(
    const float* __restrict__ xyz1,
    const float* __restrict__ xyz2)
{
    const int dir   = blockIdx.z & 1;
    const int split = blockIdx.z >> 1;
    const int b     = blockIdx.y;
    const float* __restrict__ q = (dir == 0) ? xyz1 : xyz2;
    const float* __restrict__ c = (dir == 0) ? xyz2 : xyz1;

    const int tile_q0 = blockIdx.x * (BT * UQ);

    u64 qx2[UQ], qy2[UQ], qz2[UQ], q22[UQ];
    float best[UQ];
    int   jg[UQ];
#pragma unroll
    for (int u = 0; u < UQ; ++u) {
        const int qi = b * NPTS + tile_q0 + u * BT + threadIdx.x;
        const float* p = q + 3 * qi;
        const float x0 = p[0], x1 = p[1], x2v = p[2];
        const float s = sqnorm_ref(x0, x1, x2v);
        qx2[u] = pack2(x0, x0);
        qy2[u] = pack2(x1, x1);
        qz2[u] = pack2(x2v, x2v);
        q22[u] = pack2(s, s);
        best[u] = 3.402823466e38f;
        jg[u]   = 0;
    }
    const u64 m2two = pack2(-2.0f, -2.0f);

    // smem per candidate pair p (cands 2p, 2p+1):
    //   sc[p][0] = (x_2p, x_2p1, y_2p, y_2p1)
    //   sc[p][1] = (z_2p, z_2p1, w_2p, w_2p1)   w = ||y||^2
    __shared__ float4 sc[CHUNK / 2][2];
    const int cbase3 = b * NPTS * 3;
    const int cstart = split * CPS;

    for (int c0 = cstart; c0 < cstart + CPS; c0 += CHUNK) {
        for (int pp = threadIdx.x; pp < CHUNK / 2; pp += BT) {
            const float* p0 = c + cbase3 + 3 * (c0 + 2 * pp);
            const float a0 = p0[0], a1 = p0[1], a2 = p0[2];
            const float b0 = p0[3], b1 = p0[4], b2 = p0[5];
            sc[pp][0] = make_float4(a0, b0, a1, b1);
            sc[pp][1] = make_float4(a2, b2, sqnorm_ref(a0, a1, a2),
                                            sqnorm_ref(b0, b1, b2));
        }
        __syncthreads();

        const ulonglong2* __restrict__ sp = (const ulonglong2*)sc;
        const int gb = c0 / GRP;   // global group index of first group in chunk

#pragma unroll 4
        for (int k = 0; k < CHUNK / GRP; ++k) {
            // group of 8 candidates = 4 pairs
            ulonglong2 A0 = sp[8 * k + 0], B0 = sp[8 * k + 1];
            ulonglong2 A1 = sp[8 * k + 2], B1 = sp[8 * k + 3];
            ulonglong2 A2 = sp[8 * k + 4], B2 = sp[8 * k + 5];
            ulonglong2 A3 = sp[8 * k + 6], B3 = sp[8 * k + 7];
            const int gi = gb + k;
#pragma unroll
            for (int u = 0; u < UQ; ++u) {
                u64 d0 = fma2(m2two, fma2(qz2[u], B0.x, fma2(qy2[u], A0.y, mul2(qx2[u], A0.x))), add2(q22[u], B0.y));
                u64 d1 = fma2(m2two, fma2(qz2[u], B1.x, fma2(qy2[u], A1.y, mul2(qx2[u], A1.x))), add2(q22[u], B1.y));
                u64 d2 = fma2(m2two, fma2(qz2[u], B2.x, fma2(qy2[u], A2.y, mul2(qx2[u], A2.x))), add2(q22[u], B2.y));
                u64 d3 = fma2(m2two, fma2(qz2[u], B3.x, fma2(qy2[u], A3.y, mul2(qx2[u], A3.x))), add2(q22[u], B3.y));
                float f0, f1, f2, f3, f4, f5, f6, f7;
                unpack2(d0, f0, f1); unpack2(d1, f2, f3);
                unpack2(d2, f4, f5); unpack2(d3, f6, f7);
                const float m = fminf(fminf(fminf(f0, f1), fminf(f2, f3)),
                                      fminf(fminf(f4, f5), fminf(f6, f7)));
                // SEL form: pred consumed as data (4cyc), not as guard (13cyc)
                jg[u]   = (m < best[u]) ? gi : jg[u];
                best[u] = fminf(best[u], m);
            }
        }
        __syncthreads();
    }

#pragma unroll
    for (int u = 0; u < UQ; ++u) {
        const int qg = b * NPTS + tile_q0 + u * BT + threadIdx.x;
        g_best[split][dir][qg] = best[u];
        g_jgrp[split][dir][qg] = jg[u];
    }
}

// Finalize: merge splits (ascending, strict < -> earliest split wins ties),
// then resolve the exact index inside the winning group of 8 by bit-identical
// recompute + descending equality scan (first match wins).
__global__ __launch_bounds__(256) void chamfer_nn_finalize(
    const float* __restrict__ xyz1,
    const float* __restrict__ xyz2,
    float* __restrict__ out)
{
    const int t = blockIdx.x * blockDim.x + threadIdx.x;   // [0, 2*BATCH*NPTS)
    const int BN  = BATCH * NPTS;
    const int dir = t / BN;
    const int qg  = t - dir * BN;
    const int b   = qg / NPTS;

    const float* __restrict__ q = (dir == 0) ? xyz1 : xyz2;
    const float* __restrict__ c = (dir == 0) ? xyz2 : xyz1;

    const float* qp = q + 3 * qg;
    const float qx = qp[0], qy = qp[1], qz = qp[2];
    const float q2 = sqnorm_ref(qx, qy, qz);
    const int cbase3 = b * NPTS * 3;

    // merge splits ascending: strict < keeps earliest split on ties
    float bbest = g_best[0][dir][qg];
    int   bgrp  = g_jgrp[0][dir][qg];
#pragma unroll
    for (int s = 1; s < NSPLIT; ++s) {
        const float bs = g_best[s][dir][qg];
        const int   js = g_jgrp[s][dir][qg];
        const bool take = bs < bbest;
        bbest = take ? bs : bbest;
        bgrp  = take ? js : bgrp;
    }

    // resolve exact index within the winning group of 8
    const int base = bgrp * GRP;
    int found = base;
#pragma unroll
    for (int k = GRP - 1; k >= 0; --k) {   // descending: lowest match wins
        const float* cp = c + cbase3 + 3 * (base + k);
        const float d = dist_ref(qx, qy, qz, q2, cp[0], cp[1], cp[2]);
        if (d == bbest) found = base + k;
    }

    out[dir * BN + qg]          = bbest;
    out[2 * BN + dir * BN + qg] = (float)found;
}

extern "C" void kernel_launch(void* const* d_in, const int* in_sizes, int n_in,
                              void* d_out, int out_size)
{
    (void)in_sizes; (void)n_in; (void)out_size;
    const float* xyz1 = (const float*)d_in[0];
    const float* xyz2 = (const float*)d_in[1];
    float* out = (float*)d_out;

    dim3 grid(NPTS / (BT * UQ), BATCH, 2 * NSPLIT);   // (16, 16, 8) = 2048 blocks
    chamfer_nn_main<<<grid, BT>>>(xyz1, xyz2);

    chamfer_nn_finalize<<<(2 * BATCH * NPTS) / 256, 256>>>(xyz1, xyz2, out);
}